// round 2
// baseline (speedup 1.0000x reference)
#include <cuda_runtime.h>
#include <cstdint>
#include <cstddef>

// ---------------------------------------------------------------------------
// MSRResNetKPN forward, fp32 direct conv built on packed fma.rn.f32x2 (FFMA2).
// B=4, H=W=256. All convs 3x3 SAME stride 1 (cross-correlation, XLA style).
// ---------------------------------------------------------------------------

#define ACT_NONE  0
#define ACT_RELU  1
#define ACT_LRELU 2

static constexpr int Hh = 256;
static constexpr int Ww = 256;
static constexpr int Bb = 4;
static constexpr size_t HW = (size_t)Hh * Ww;   // 65536

// ---- scratch (static __device__ arrays: allocation-free) ----
__device__ float g_fea1 [Bb * 64  * HW];
__device__ float g_fea  [Bb * 64  * HW];
__device__ float g_tmp  [Bb * 64  * HW];
__device__ float g_feat [Bb * 128 * HW];
__device__ float g_core [Bb * 75  * HW];
__device__ float g_resid[Bb * 3   * HW];

// ---- f32x2 helpers ----
__device__ __forceinline__ unsigned long long pk2(float lo, float hi) {
    unsigned long long r;
    asm("mov.b64 %0, {%1, %2};" : "=l"(r) : "f"(lo), "f"(hi));
    return r;
}
__device__ __forceinline__ void upk2(unsigned long long v, float& lo, float& hi) {
    asm("mov.b64 {%0, %1}, %2;" : "=f"(lo), "=f"(hi) : "l"(v));
}
__device__ __forceinline__ unsigned long long f2fma(unsigned long long a,
                                                    unsigned long long b,
                                                    unsigned long long c) {
    unsigned long long d;
    asm("fma.rn.f32x2 %0, %1, %2, %3;" : "=l"(d) : "l"(a), "l"(b), "l"(c));
    return d;
}

// ---------------------------------------------------------------------------
// Direct 3x3 conv. Tile: 8 rows x 32 cols of output per block, all OC chans.
// Block (16,4,4): tx = pair-column, ty = row-pair (2 rows), tz = OC slab.
// Each thread: 2 rows x 1 pixel-pair x SLAB output channels.
// ---------------------------------------------------------------------------
template <int IC, int OC, int ACT, bool ACCUM>
__global__ void __launch_bounds__(256, (((OC + 3) / 4) <= 16) ? 2 : 1)
conv3x3_kernel(const float* __restrict__ in, const float* __restrict__ wgt,
               const float* __restrict__ bias, float* __restrict__ out,
               int oct /* total channels of output buffer */) {
    constexpr int ICS  = (IC % 4 == 0) ? 4 : IC;   // channels staged per pass
    constexpr int NSTG = IC / ICS;
    constexpr int SLAB = (OC + 3) / 4;
    constexpr bool GUARD = (OC % 4) != 0;

    __shared__ float s_in[ICS][10][36];
    __shared__ __align__(16) unsigned long long s_w[ICS][OC][10];

    const int tx = threadIdx.x;            // 0..15
    const int ty = threadIdx.y;            // 0..3
    const int tz = threadIdx.z;            // 0..3
    const int tid = tx + (ty << 4) + (tz << 6);
    const int b  = blockIdx.z;
    const int y0 = blockIdx.y * 8;
    const int x0 = blockIdx.x * 32;
    const int oc0 = tz * SLAB;

    unsigned long long acc[SLAB][2];
#pragma unroll
    for (int o = 0; o < SLAB; ++o) {
        float bv = 0.f;
        if (!GUARD || (oc0 + o) < OC) bv = bias[oc0 + o];
        acc[o][0] = pk2(bv, bv);
        acc[o][1] = acc[o][0];
    }

#pragma unroll 1
    for (int s = 0; s < NSTG; ++s) {
        const int ic0 = s * ICS;
        if (s) __syncthreads();   // protect smem reuse across stages

        // stage input tile (10 x 34 per channel, zero-padded halo)
        for (int i = tid; i < ICS * 340; i += 256) {
            int ci = i % 34;
            int t  = i / 34;
            int ri = t % 10;
            int ch = t / 10;
            int gy = y0 - 1 + ri;
            int gx = x0 - 1 + ci;
            float v = 0.f;
            if ((unsigned)gy < 256u && (unsigned)gx < 256u)
                v = in[(((size_t)b * IC + ic0 + ch) * Hh + gy) * Ww + gx];
            s_in[ch][ri][ci] = v;
        }
        // stage packed (w,w) weights: layout [ic][oc][k], k padded to 10
        for (int i = tid; i < ICS * OC * 9; i += 256) {
            int k  = i % 9;
            int t  = i / 9;
            int oc = t % OC;
            int ch = t / OC;
            float wv = wgt[((size_t)oc * IC + ic0 + ch) * 9 + k];
            s_w[ch][oc][k] = pk2(wv, wv);
        }
        __syncthreads();

#pragma unroll 1
        for (int ch = 0; ch < ICS; ++ch) {
            // 4 rows x 4 cols of input per thread
            float v[4][4];
#pragma unroll
            for (int r = 0; r < 4; ++r)
#pragma unroll
                for (int c = 0; c < 4; ++c)
                    v[r][c] = s_in[ch][2 * ty + r][2 * tx + c];
            // shifted pixel-pair packs
            unsigned long long p[4][3];
#pragma unroll
            for (int r = 0; r < 4; ++r) {
                p[r][0] = pk2(v[r][0], v[r][1]);
                p[r][1] = pk2(v[r][1], v[r][2]);
                p[r][2] = pk2(v[r][2], v[r][3]);
            }
#pragma unroll
            for (int o = 0; o < SLAB; ++o) {
                if (GUARD && (oc0 + o) >= OC) continue;
                const ulonglong2* wp =
                    reinterpret_cast<const ulonglong2*>(&s_w[ch][oc0 + o][0]);
                ulonglong2 w01 = wp[0], w23 = wp[1], w45 = wp[2], w67 = wp[3];
                unsigned long long w8 = s_w[ch][oc0 + o][8];
                // k = 3*ki + kj ; row r uses p[r+ki][kj]
                acc[o][0] = f2fma(p[0][0], w01.x, acc[o][0]);
                acc[o][1] = f2fma(p[1][0], w01.x, acc[o][1]);
                acc[o][0] = f2fma(p[0][1], w01.y, acc[o][0]);
                acc[o][1] = f2fma(p[1][1], w01.y, acc[o][1]);
                acc[o][0] = f2fma(p[0][2], w23.x, acc[o][0]);
                acc[o][1] = f2fma(p[1][2], w23.x, acc[o][1]);
                acc[o][0] = f2fma(p[1][0], w23.y, acc[o][0]);
                acc[o][1] = f2fma(p[2][0], w23.y, acc[o][1]);
                acc[o][0] = f2fma(p[1][1], w45.x, acc[o][0]);
                acc[o][1] = f2fma(p[2][1], w45.x, acc[o][1]);
                acc[o][0] = f2fma(p[1][2], w45.y, acc[o][0]);
                acc[o][1] = f2fma(p[2][2], w45.y, acc[o][1]);
                acc[o][0] = f2fma(p[2][0], w67.x, acc[o][0]);
                acc[o][1] = f2fma(p[3][0], w67.x, acc[o][1]);
                acc[o][0] = f2fma(p[2][1], w67.y, acc[o][0]);
                acc[o][1] = f2fma(p[3][1], w67.y, acc[o][1]);
                acc[o][0] = f2fma(p[2][2], w8,    acc[o][0]);
                acc[o][1] = f2fma(p[3][2], w8,    acc[o][1]);
            }
        }
    }

    // store / accumulate
#pragma unroll
    for (int o = 0; o < SLAB; ++o) {
        int oc = oc0 + o;
        if (GUARD && oc >= OC) continue;
#pragma unroll
        for (int r = 0; r < 2; ++r) {
            float lo, hi;
            upk2(acc[o][r], lo, hi);
            if (ACT == ACT_RELU) {
                lo = fmaxf(lo, 0.f);
                hi = fmaxf(hi, 0.f);
            } else if (ACT == ACT_LRELU) {
                lo = lo > 0.f ? lo : 0.1f * lo;
                hi = hi > 0.f ? hi : 0.1f * hi;
            }
            size_t oi = (((size_t)b * oct + oc) * Hh + (y0 + 2 * ty + r)) * Ww +
                        (x0 + 2 * tx);
            float2* po = reinterpret_cast<float2*>(out + oi);
            if (ACCUM) {
                float2 cur = *po;
                cur.x += lo;
                cur.y += hi;
                *po = cur;
            } else {
                float2 vv;
                vv.x = lo;
                vv.y = hi;
                *po = vv;
            }
        }
    }
}

// fea = fea1 (vectorized copy)
__global__ void copy4_kernel(const float4* __restrict__ src,
                             float4* __restrict__ dst, int n4) {
    int i = blockIdx.x * blockDim.x + threadIdx.x;
    if (i < n4) dst[i] = src[i];
}

// feat[:, 64:128] = fea + fea1
__global__ void add_feat_kernel(const float4* __restrict__ fea,
                                const float4* __restrict__ fea1,
                                float4* __restrict__ feat) {
    int i = blockIdx.x * blockDim.x + threadIdx.x;   // over 4 * 64*HW/4
    const int per_b = (int)(64 * HW / 4);            // 1048576
    if (i >= Bb * per_b) return;
    int b = i / per_b;
    int r = i - b * per_b;
    float4 a = fea[(size_t)b * per_b + r];
    float4 c = fea1[(size_t)b * per_b + r];
    float4 o;
    o.x = a.x + c.x; o.y = a.y + c.y; o.z = a.z + c.z; o.w = a.w + c.w;
    feat[((size_t)b * 128 + 64) * (HW / 4) + r] = o;
}

// out[b,c,h,w] = sum_{k in 5x5} x[b,c,h+ki-2,w+kj-2] * core[b, c*25+k, h, w]
//               + resid[b,c,h,w]
__global__ void kpn_kernel(const float* __restrict__ x,
                           const float* __restrict__ core,
                           const float* __restrict__ resid,
                           float* __restrict__ out) {
    int idx = blockIdx.x * blockDim.x + threadIdx.x;
    const int n = Bb * 3 * (int)HW;
    if (idx >= n) return;
    int w = idx & 255;
    int h = (idx >> 8) & 255;
    int c = (idx >> 16) % 3;
    int b = idx / (3 * (int)HW);

    float s = resid[idx];
    size_t cb = (((size_t)b * 75 + (size_t)c * 25) * Hh + h) * Ww + w;
    size_t xb = ((size_t)b * 3 + c) * HW;
#pragma unroll
    for (int ki = 0; ki < 5; ++ki) {
        int gy = h + ki - 2;
        bool oky = (unsigned)gy < 256u;
#pragma unroll
        for (int kj = 0; kj < 5; ++kj) {
            int gx = w + kj - 2;
            float xv = 0.f;
            if (oky && (unsigned)gx < 256u)
                xv = x[xb + (size_t)gy * Ww + gx];
            s += xv * core[cb + (size_t)(ki * 5 + kj) * HW];
        }
    }
    out[idx] = s;
}

// ---------------------------------------------------------------------------
extern "C" void kernel_launch(void* const* d_in, const int* in_sizes, int n_in,
                              void* d_out, int out_size) {
    const float* x       = (const float*)d_in[0];
    const float* w_first = (const float*)d_in[1];
    const float* b_first = (const float*)d_in[2];
    const float* w_trunk = (const float*)d_in[3];
    const float* b_trunk = (const float*)d_in[4];
    const float* c1_w    = (const float*)d_in[5];
    const float* c1_b    = (const float*)d_in[6];
    const float* c2_w1   = (const float*)d_in[7];
    const float* c2_b1   = (const float*)d_in[8];
    const float* c2_w2   = (const float*)d_in[9];
    const float* c2_b2   = (const float*)d_in[10];
    const float* c3_w1   = (const float*)d_in[11];
    const float* c3_b1   = (const float*)d_in[12];
    const float* c3_w2   = (const float*)d_in[13];
    const float* c3_b2   = (const float*)d_in[14];
    const float* c3_w3   = (const float*)d_in[15];
    const float* c3_b3   = (const float*)d_in[16];

    float *fea1, *fea, *tmp, *feat, *core, *resid;
    cudaGetSymbolAddress((void**)&fea1,  g_fea1);
    cudaGetSymbolAddress((void**)&fea,   g_fea);
    cudaGetSymbolAddress((void**)&tmp,   g_tmp);
    cudaGetSymbolAddress((void**)&feat,  g_feat);
    cudaGetSymbolAddress((void**)&core,  g_core);
    cudaGetSymbolAddress((void**)&resid, g_resid);

    const dim3 grid(Ww / 32, Hh / 8, Bb);   // (8, 32, 4)
    const dim3 blk(16, 4, 4);

    // 1) fea1 = lrelu(conv_first(x))
    conv3x3_kernel<3, 64, ACT_LRELU, false><<<grid, blk>>>(x, w_first, b_first,
                                                           fea1, 64);
    // 2) fea = fea1
    {
        int n4 = (int)(Bb * 64 * HW / 4);
        copy4_kernel<<<(n4 + 255) / 256, 256>>>((const float4*)fea1,
                                                (float4*)fea, n4);
    }
    // 3) 16 residual blocks: fea += conv2(relu(conv1(fea)))
    for (int i = 0; i < 16; ++i) {
        const float* w1 = w_trunk + (size_t)(2 * i) * 64 * 64 * 9;
        const float* b1 = b_trunk + (size_t)(2 * i) * 64;
        const float* w2 = w_trunk + (size_t)(2 * i + 1) * 64 * 64 * 9;
        const float* b2 = b_trunk + (size_t)(2 * i + 1) * 64;
        conv3x3_kernel<64, 64, ACT_RELU, false><<<grid, blk>>>(fea, w1, b1,
                                                               tmp, 64);
        conv3x3_kernel<64, 64, ACT_NONE, true><<<grid, blk>>>(tmp, w2, b2,
                                                              fea, 64);
    }
    // 4) feat[:,64:] = fea + fea1  (global residual folded into concat)
    {
        int n4 = (int)(Bb * 64 * HW / 4);
        add_feat_kernel<<<(n4 + 255) / 256, 256>>>(
            (const float4*)fea, (const float4*)fea1, (float4*)feat);
    }
    // 5) c3 branch -> feat[:, :64]
    conv3x3_kernel<3, 64, ACT_RELU, false><<<grid, blk>>>(x, c3_w1, c3_b1,
                                                          tmp, 64);
    conv3x3_kernel<64, 64, ACT_RELU, false><<<grid, blk>>>(tmp, c3_w2, c3_b2,
                                                           fea1, 64);
    conv3x3_kernel<64, 64, ACT_NONE, false><<<grid, blk>>>(fea1, c3_w3, c3_b3,
                                                           feat, 128);
    // 6) residual branch: conv2( relu(conv1(feat)) )
    conv3x3_kernel<128, 64, ACT_RELU, false><<<grid, blk>>>(feat, c2_w1, c2_b1,
                                                            tmp, 64);
    conv3x3_kernel<64, 3, ACT_NONE, false><<<grid, blk>>>(tmp, c2_w2, c2_b2,
                                                          resid, 3);
    // 7) core = conv1(feat): per-pixel 5x5 kernels
    conv3x3_kernel<128, 75, ACT_NONE, false><<<grid, blk>>>(feat, c1_w, c1_b,
                                                            core, 75);
    // 8) KPN gather + residual
    {
        int n = Bb * 3 * (int)HW;
        kpn_kernel<<<(n + 255) / 256, 256>>>(x, core, resid, (float*)d_out);
    }
    (void)in_sizes; (void)n_in; (void)out_size;
}